// round 2
// baseline (speedup 1.0000x reference)
#include <cuda_runtime.h>
#include <math.h>

#define B_ 16
#define T_ 2048
#define C_ 1024
#define H_ 64
#define ROWS_ (B_ * T_)   // 32768

// Scratch for projected q, k, v  (8 MB each; static __device__ allocation is allowed)
__device__ float g_q[ROWS_ * H_];
__device__ float g_k[ROWS_ * H_];
__device__ float g_v[ROWS_ * H_];

// log2(e) / sqrt(H) folded into q so attention uses exp2f directly
#define QSCALE 0.18033688011112042f   // 1.4426950408889634f * 0.125f

// ---------------------------------------------------------------------------
// Kernel 1: QKV projection.  C = X[32768,1024] @ W[1024,64] for each of q/k/v.
// Tile: BM=128, BN=64, BK=32, 256 threads, 8x4 register tile per thread.
// ---------------------------------------------------------------------------
__global__ __launch_bounds__(256, 3)
void qkv_proj_kernel(const float* __restrict__ x,
                     const float* __restrict__ wq,
                     const float* __restrict__ wk,
                     const float* __restrict__ wv)
{
    __shared__ float As[32][132];   // A^T tile, pad 132 to reduce transpose STS conflicts
    __shared__ float Bs[32][64];

    const int which = blockIdx.y;
    const float* __restrict__ w = (which == 0) ? wq : (which == 1) ? wk : wv;
    float* __restrict__ outp     = (which == 0) ? g_q : (which == 1) ? g_k : g_v;

    const int rowBase = blockIdx.x * 128;
    const int tid = threadIdx.x;
    const int tx  = tid & 15;   // output col group: cols 4*tx .. 4*tx+3
    const int ty  = tid >> 4;   // output row group: rows 8*ty .. 8*ty+7

    float acc[8][4];
#pragma unroll
    for (int m = 0; m < 8; m++)
#pragma unroll
        for (int n = 0; n < 4; n++) acc[m][n] = 0.0f;

    for (int kt = 0; kt < C_; kt += 32) {
        // --- load A tile (128 rows x 32 k), store transposed ---
#pragma unroll
        for (int it = 0; it < 4; it++) {
            int f4 = tid + it * 256;
            int r  = f4 >> 3;       // 0..127
            int c4 = f4 & 7;        // 0..7
            float4 v = *(const float4*)&x[(size_t)(rowBase + r) * C_ + kt + c4 * 4];
            As[c4 * 4 + 0][r] = v.x;
            As[c4 * 4 + 1][r] = v.y;
            As[c4 * 4 + 2][r] = v.z;
            As[c4 * 4 + 3][r] = v.w;
        }
        // --- load B tile (32 k x 64 n) ---
#pragma unroll
        for (int it = 0; it < 2; it++) {
            int f4 = tid + it * 256;
            int kr = f4 >> 4;       // 0..31
            int c4 = f4 & 15;       // 0..15
            *(float4*)&Bs[kr][c4 * 4] =
                *(const float4*)&w[(size_t)(kt + kr) * H_ + c4 * 4];
        }
        __syncthreads();

#pragma unroll 8
        for (int k = 0; k < 32; k++) {
            float4 b0 = *(const float4*)&Bs[k][tx * 4];
            float4 a0 = *(const float4*)&As[k][ty * 8];
            float4 a1 = *(const float4*)&As[k][ty * 8 + 4];
            float av[8] = {a0.x, a0.y, a0.z, a0.w, a1.x, a1.y, a1.z, a1.w};
            float bv[4] = {b0.x, b0.y, b0.z, b0.w};
#pragma unroll
            for (int m = 0; m < 8; m++)
#pragma unroll
                for (int n = 0; n < 4; n++)
                    acc[m][n] += av[m] * bv[n];
        }
        __syncthreads();
    }

    const float s = (which == 0) ? QSCALE : 1.0f;
#pragma unroll
    for (int m = 0; m < 8; m++) {
        float4 o;
        o.x = acc[m][0] * s; o.y = acc[m][1] * s;
        o.z = acc[m][2] * s; o.w = acc[m][3] * s;
        *(float4*)&outp[(size_t)(rowBase + ty * 8 + m) * H_ + tx * 4] = o;
    }
}

// ---------------------------------------------------------------------------
// Kernel 2: causal flash attention.  BQ = BKV = 64, 128 threads.
// Thread (i = tid/16, j = tid%16): S micro-tile 8q x 4kv, O micro-tile 8q x 4h.
// P tile aliased onto the K smem buffer (K dead after S).  K tile XOR-swizzled.
// Blocks paired over q-tiles (qt, 31-qt) -> uniform 33 kv-tiles per block.
// ---------------------------------------------------------------------------
__global__ __launch_bounds__(128, 3)
void attn_kernel(float* __restrict__ out)
{
    __shared__ float Qs[64][64];
    __shared__ float KPs[64][64];   // K (swizzled) then re-used as P (plain)
    __shared__ float Vs[64][64];

    const int tid = threadIdx.x;
    const int j = tid & 15;    // kv-col group (S) / h-col group (O)
    const int i = tid >> 4;    // q-row group (rows 8i..8i+7)

    const int b = blockIdx.x >> 4;
    const int p = blockIdx.x & 15;
    const size_t bRow = (size_t)b * T_;   // row offset of this batch

    for (int half = 0; half < 2; half++) {
        const int qt = (half == 0) ? p : (31 - p);
        const int qBase = qt * 64;

        // load Q tile
#pragma unroll
        for (int it = 0; it < 8; it++) {
            int f4 = tid + it * 128;
            int r = f4 >> 4, c = f4 & 15;
            *(float4*)&Qs[r][c * 4] =
                *(const float4*)&g_q[(bRow + qBase + r) * H_ + c * 4];
        }

        float m_i[8], l_i[8], acc[8][4];
#pragma unroll
        for (int m = 0; m < 8; m++) {
            m_i[m] = -1e30f; l_i[m] = 0.0f;
#pragma unroll
            for (int n = 0; n < 4; n++) acc[m][n] = 0.0f;
        }

        for (int kt = 0; kt <= qt; kt++) {
            const int kvBase = kt * 64;
            // load K (swizzled) and V tiles
#pragma unroll
            for (int it = 0; it < 8; it++) {
                int f4 = tid + it * 128;
                int r = f4 >> 4, c = f4 & 15;
                int cp = c ^ (r >> 2);
                *(float4*)&KPs[r][cp * 4] =
                    *(const float4*)&g_k[(bRow + kvBase + r) * H_ + c * 4];
                *(float4*)&Vs[r][c * 4] =
                    *(const float4*)&g_v[(bRow + kvBase + r) * H_ + c * 4];
            }
            __syncthreads();

            // ---- S = Q K^T  (S[m][n]: q row 8i+m, kv col 4j+n) ----
            float S[8][4];
#pragma unroll
            for (int m = 0; m < 8; m++)
#pragma unroll
                for (int n = 0; n < 4; n++) S[m][n] = 0.0f;

#pragma unroll 4
            for (int h4 = 0; h4 < 16; h4++) {
                float4 kf[4];
#pragma unroll
                for (int n = 0; n < 4; n++)
                    kf[n] = *(const float4*)&KPs[4 * j + n][4 * (h4 ^ j)];
#pragma unroll
                for (int m = 0; m < 8; m++) {
                    float4 a = *(const float4*)&Qs[8 * i + m][4 * h4];
#pragma unroll
                    for (int n = 0; n < 4; n++) {
                        S[m][n] += a.x * kf[n].x;
                        S[m][n] += a.y * kf[n].y;
                        S[m][n] += a.z * kf[n].z;
                        S[m][n] += a.w * kf[n].w;
                    }
                }
            }
            __syncthreads();   // K reads done; KPs may now be overwritten by P

            // causal mask on the diagonal tile (kvBase == qBase there)
            if (kt == qt) {
#pragma unroll
                for (int m = 0; m < 8; m++)
#pragma unroll
                    for (int n = 0; n < 4; n++)
                        if (4 * j + n > 8 * i + m) S[m][n] = -1e30f;
            }

            // ---- online softmax; write P into KPs (plain layout) ----
#pragma unroll
            for (int m = 0; m < 8; m++) {
                float rmax = fmaxf(fmaxf(S[m][0], S[m][1]), fmaxf(S[m][2], S[m][3]));
#pragma unroll
                for (int msk = 8; msk >= 1; msk >>= 1)
                    rmax = fmaxf(rmax, __shfl_xor_sync(0xffffffffu, rmax, msk));
                float mNew = fmaxf(m_i[m], rmax);
                float factor = exp2f(m_i[m] - mNew);
                float4 pv;
                pv.x = exp2f(S[m][0] - mNew);
                pv.y = exp2f(S[m][1] - mNew);
                pv.z = exp2f(S[m][2] - mNew);
                pv.w = exp2f(S[m][3] - mNew);
                float rsum = pv.x + pv.y + pv.z + pv.w;
#pragma unroll
                for (int msk = 8; msk >= 1; msk >>= 1)
                    rsum += __shfl_xor_sync(0xffffffffu, rsum, msk);
                l_i[m] = l_i[m] * factor + rsum;
                m_i[m] = mNew;
                acc[m][0] *= factor; acc[m][1] *= factor;
                acc[m][2] *= factor; acc[m][3] *= factor;
                *(float4*)&KPs[8 * i + m][4 * j] = pv;
            }
            __syncthreads();   // P visible

            // ---- O += P V  (acc[m][c]: q row 8i+m, h col 4j+c) ----
#pragma unroll 4
            for (int kv4 = 0; kv4 < 16; kv4++) {
                float4 vf[4];
#pragma unroll
                for (int n = 0; n < 4; n++)
                    vf[n] = *(const float4*)&Vs[4 * kv4 + n][4 * j];
#pragma unroll
                for (int m = 0; m < 8; m++) {
                    float4 pm = *(const float4*)&KPs[8 * i + m][4 * kv4];
                    acc[m][0] += pm.x * vf[0].x; acc[m][0] += pm.y * vf[1].x;
                    acc[m][0] += pm.z * vf[2].x; acc[m][0] += pm.w * vf[3].x;
                    acc[m][1] += pm.x * vf[0].y; acc[m][1] += pm.y * vf[1].y;
                    acc[m][1] += pm.z * vf[2].y; acc[m][1] += pm.w * vf[3].y;
                    acc[m][2] += pm.x * vf[0].z; acc[m][2] += pm.y * vf[1].z;
                    acc[m][2] += pm.z * vf[2].z; acc[m][2] += pm.w * vf[3].z;
                    acc[m][3] += pm.x * vf[0].w; acc[m][3] += pm.y * vf[1].w;
                    acc[m][3] += pm.z * vf[2].w; acc[m][3] += pm.w * vf[3].w;
                }
            }
            __syncthreads();   // O-GEMM done before next tile overwrites K/V/P
        }

        // epilogue: normalize and store
#pragma unroll
        for (int m = 0; m < 8; m++) {
            float inv = 1.0f / l_i[m];
            float4 o;
            o.x = acc[m][0] * inv; o.y = acc[m][1] * inv;
            o.z = acc[m][2] * inv; o.w = acc[m][3] * inv;
            *(float4*)&out[(bRow + qBase + 8 * i + m) * H_ + 4 * j] = o;
        }
        __syncthreads();   // safe before next half reloads Qs
    }
}

// ---------------------------------------------------------------------------
extern "C" void kernel_launch(void* const* d_in, const int* in_sizes, int n_in,
                              void* d_out, int out_size)
{
    const float* x  = (const float*)d_in[0];
    const float* wq = (const float*)d_in[1];
    const float* wk = (const float*)d_in[2];
    const float* wv = (const float*)d_in[3];
    float* out = (float*)d_out;

    dim3 gProj(ROWS_ / 128, 3);
    qkv_proj_kernel<<<gProj, 256>>>(x, wq, wk, wv);
    attn_kernel<<<B_ * 16, 128>>>(out);
}